// round 7
// baseline (speedup 1.0000x reference)
#include <cuda_runtime.h>

// Problem constants (fixed shapes from reference setup_inputs)
#define LNM   19
#define BSZ   2
#define HH    800
#define WW    640
#define HW    (HH * WW)            // 512000
#define NPAIR (BSZ * LNM)          // 38
#define NCHUNK 50
#define TPB   256
#define F4_PER_PLANE (HW / 4)                  // 128000
#define F4_PER_CHUNK (F4_PER_PLANE / NCHUNK)   // 2560
#define ITERS (F4_PER_CHUNK / TPB)             // 10 (exact)
#define BATCH 5
#define NBLOCKS (NPAIR * NCHUNK)               // 1900
#define W4    (WW / 4)                         // 160
#define R1SQ  1681.0f              // 41*41
#define INV_R2 (1.0f / 41.0f)

#define FXSCALE 4194304.0          // 2^22
#define INV_FXSCALE (1.0 / 4194304.0)

// Deterministic cross-block accumulators: fixed-point int64 per (pair, {bce,l1x,l1y,m}).
// Integer atomic adds are associative -> bitwise deterministic result.
// All accesses (accumulate, read, reset) go through L2 atomics — no fences needed,
// no L1 state involved, safe across CUDA-graph replays.
__device__ unsigned long long g_acc[NPAIR * 4];   // zero-init; reset via atomicExch by finisher
__device__ unsigned int       g_count;            // zero-init; reset via atomicExch by finisher

__global__ __launch_bounds__(TPB) void loss_onekernel(
    const float* __restrict__ fm,   // (B, 3L, H, W)
    const float* __restrict__ lmk,  // (B, L, 2)
    float* __restrict__ out)
{
    const int pair  = blockIdx.y;           // 0..37
    const int chunk = blockIdx.x;           // 0..49
    const int b = pair / LNM;
    const int l = pair % LNM;

    // Landmark center (round-half-to-even to match jnp.round)
    const float X = rintf(lmk[(b * LNM + l) * 2 + 0] * (float)(HH - 1));
    const float Y = rintf(lmk[(b * LNM + l) * 2 + 1] * (float)(WW - 1));

    // Channel base pointers as float4 streams
    const float4* __restrict__ lg =
        (const float4*)(fm + ((size_t)b * 3 * LNM + l) * (size_t)HW);
    const float4* __restrict__ px = lg + (size_t)LNM * F4_PER_PLANE;
    const float4* __restrict__ py = px + (size_t)LNM * F4_PER_PLANE;

    float s_bce = 0.0f, s_x = 0.0f, s_y = 0.0f, s_m = 0.0f;

    const int base = chunk * F4_PER_CHUNK + threadIdx.x;

    #pragma unroll
    for (int mi = 0; mi < ITERS / BATCH; ++mi) {
        // ---- Load phase: 15 LDG.128 issued back-to-back (MLP=15) ----
        float4 x4[BATCH], px4[BATCH], py4[BATCH];
        #pragma unroll
        for (int j = 0; j < BATCH; ++j) {
            const int p4 = base + (mi * BATCH + j) * TPB;
            x4[j]  = __ldg(&lg[p4]);
            px4[j] = __ldg(&px[p4]);
            py4[j] = __ldg(&py[p4]);
        }

        // ---- Compute phase ----
        #pragma unroll
        for (int j = 0; j < BATCH; ++j) {
            const int p4 = base + (mi * BATCH + j) * TPB;
            const int h  = p4 / W4;
            const int w  = (p4 - h * W4) * 4;

            const float dx   = X - (float)h;
            const float dx2  = dx * dx;
            const float offx = dx * INV_R2;

            const float xs[4]  = {x4[j].x,  x4[j].y,  x4[j].z,  x4[j].w};
            const float pxs[4] = {px4[j].x, px4[j].y, px4[j].z, px4[j].w};
            const float pys[4] = {py4[j].x, py4[j].y, py4[j].z, py4[j].w};

            #pragma unroll
            for (int k = 0; k < 4; ++k) {
                const float dy   = Y - (float)(w + k);
                const float r2   = fmaf(dy, dy, dx2);
                const float heat = (r2 <= R1SQ) ? 1.0f : 0.0f;

                // BCE-with-logits: softplus(x) - x*heat
                const float x  = xs[k];
                const float sp = fmaxf(x, 0.0f) + __logf(1.0f + __expf(-fabsf(x)));
                s_bce += sp - x * heat;

                // Masked L1 for offsets
                const float vx = fabsf(pxs[k] - offx);
                const float vy = fabsf(pys[k] - dy * INV_R2);
                s_x = fmaf(heat, vx, s_x);
                s_y = fmaf(heat, vy, s_y);
                s_m += heat;
            }
        }
    }

    // Block reduction of 4 accumulators (warp shuffle + smem)
    const unsigned FULL = 0xFFFFFFFFu;
    #pragma unroll
    for (int off = 16; off > 0; off >>= 1) {
        s_bce += __shfl_down_sync(FULL, s_bce, off);
        s_x   += __shfl_down_sync(FULL, s_x,   off);
        s_y   += __shfl_down_sync(FULL, s_y,   off);
        s_m   += __shfl_down_sync(FULL, s_m,   off);
    }

    __shared__ float smem[4][TPB / 32];
    const int lane = threadIdx.x & 31;
    const int wid  = threadIdx.x >> 5;
    if (lane == 0) {
        smem[0][wid] = s_bce;
        smem[1][wid] = s_x;
        smem[2][wid] = s_y;
        smem[3][wid] = s_m;
    }
    __syncthreads();

    __shared__ bool is_last;
    if (threadIdx.x == 0) {
        float v0 = 0.0f, v1 = 0.0f, v2 = 0.0f, v3 = 0.0f;
        #pragma unroll
        for (int i = 0; i < TPB / 32; ++i) {
            v0 += smem[0][i];
            v1 += smem[1][i];
            v2 += smem[2][i];
            v3 += smem[3][i];
        }
        // Fixed-point, deterministic accumulation at L2 (atomics bypass L1; no fence).
        unsigned long long f0 = (unsigned long long)(long long)llrint((double)v0 * FXSCALE);
        unsigned long long f1 = (unsigned long long)(long long)llrint((double)v1 * FXSCALE);
        unsigned long long f2 = (unsigned long long)(long long)llrint((double)v2 * FXSCALE);
        unsigned long long f3 = (unsigned long long)(long long)llrint((double)v3 * FXSCALE);
        unsigned long long r = 0;
        r ^= atomicAdd(&g_acc[pair * 4 + 0], f0);
        r ^= atomicAdd(&g_acc[pair * 4 + 1], f1);
        r ^= atomicAdd(&g_acc[pair * 4 + 2], f2);
        r ^= atomicAdd(&g_acc[pair * 4 + 3], f3);
        unsigned int prev = atomicAdd(&g_count, 1u);
        // r-dependency: is_last can only be decided after this block's accumulator
        // atomics have been performed at L2 (their return values are consumed here).
        is_last = (prev == NBLOCKS - 1) && (r != 0x5DEADBEEFDEADBEEull);
    }
    __syncthreads();

    if (!is_last) return;

    // ---- Finisher: exactly one block (the last to arrive at g_count). All other
    // blocks' accumulator atomics are ordered before their g_count increment, so
    // the totals are complete. Read+reset via atomicExch (same L2 atomic unit).
    const int t = threadIdx.x;
    float pl = 0.0f;
    if (t < NPAIR) {
        unsigned long long ub = atomicExch(&g_acc[t * 4 + 0], 0ull);
        unsigned long long ux = atomicExch(&g_acc[t * 4 + 1], 0ull);
        unsigned long long uy = atomicExch(&g_acc[t * 4 + 2], 0ull);
        unsigned long long um = atomicExch(&g_acc[t * 4 + 3], 0ull);
        const double sb = (double)(long long)ub * INV_FXSCALE;
        const double sx = (double)(long long)ux * INV_FXSCALE;
        const double sy = (double)(long long)uy * INV_FXSCALE;
        const double sm = (double)(long long)um * INV_FXSCALE;
        pl = (float)(2.0 * sb / (double)HW + sx / sm + sy / sm);
    }
    if (t == 0) atomicExch(&g_count, 0u);

    __shared__ float red[64];
    if (t < 64) red[t] = (t < NPAIR) ? pl : 0.0f;
    __syncthreads();
    #pragma unroll
    for (int s = 32; s > 0; s >>= 1) {
        if (t < s) red[t] += red[t + s];
        __syncthreads();
    }
    if (t == 0) out[0] = red[0] / (float)NPAIR;
}

extern "C" void kernel_launch(void* const* d_in, const int* in_sizes, int n_in,
                              void* d_out, int out_size)
{
    const float* fm  = (const float*)d_in[0];
    const float* lmk = (const float*)d_in[1];
    float* out = (float*)d_out;

    dim3 grid(NCHUNK, NPAIR);
    loss_onekernel<<<grid, TPB>>>(fm, lmk, out);
}

// round 8
// speedup vs baseline: 1.2168x; 1.2168x over previous
#include <cuda_runtime.h>

// Problem constants (fixed shapes from reference setup_inputs)
#define LNM   19
#define BSZ   2
#define HH    800
#define WW    640
#define HW    (HH * WW)            // 512000
#define NPAIR (BSZ * LNM)          // 38
#define NCHUNK 50
#define TPB   256
#define F4_PER_PLANE (HW / 4)                  // 128000
#define F4_PER_CHUNK (F4_PER_PLANE / NCHUNK)   // 2560
#define ITERS (F4_PER_CHUNK / TPB)             // 10 (exact)
#define BATCH 5
#define NMACRO (ITERS / BATCH)                 // 2
#define W4    (WW / 4)                         // 160
#define R1SQ  1681.0f              // 41*41
#define INV_R2 (1.0f / 41.0f)

// Scratch: per-(pair,chunk) partial sums as float4 {bce, l1x, l1y, msum}
__device__ float4 g_partial[NPAIR * NCHUNK];

__global__ __launch_bounds__(TPB, 3) void loss_main_kernel(
    const float* __restrict__ fm,   // (B, 3L, H, W)
    const float* __restrict__ lmk)  // (B, L, 2)
{
    const int pair  = blockIdx.y;           // 0..37
    const int chunk = blockIdx.x;           // 0..49
    const int b = pair / LNM;
    const int l = pair % LNM;

    // Landmark center (round-half-to-even to match jnp.round)
    const float X = rintf(lmk[(b * LNM + l) * 2 + 0] * (float)(HH - 1));
    const float Y = rintf(lmk[(b * LNM + l) * 2 + 1] * (float)(WW - 1));

    // Channel base pointers as float4 streams
    const float4* __restrict__ lg =
        (const float4*)(fm + ((size_t)b * 3 * LNM + l) * (size_t)HW);
    const float4* __restrict__ px = lg + (size_t)LNM * F4_PER_PLANE;
    const float4* __restrict__ py = px + (size_t)LNM * F4_PER_PLANE;

    float s_bce = 0.0f, s_x = 0.0f, s_y = 0.0f, s_m = 0.0f;

    const int base = chunk * F4_PER_CHUNK + threadIdx.x;

    // Double-buffered register pipeline: batch mi+1's 15 LDG.128 are issued
    // BEFORE batch mi's compute, so loads stay in flight across compute.
    float4 x4[2][BATCH], px4[2][BATCH], py4[2][BATCH];

    #pragma unroll
    for (int j = 0; j < BATCH; ++j) {
        const int p4 = base + j * TPB;
        x4[0][j]  = __ldg(&lg[p4]);
        px4[0][j] = __ldg(&px[p4]);
        py4[0][j] = __ldg(&py[p4]);
    }

    #pragma unroll
    for (int mi = 0; mi < NMACRO; ++mi) {
        const int cur = mi & 1;
        // Prefetch next batch
        if (mi + 1 < NMACRO) {
            #pragma unroll
            for (int j = 0; j < BATCH; ++j) {
                const int p4 = base + ((mi + 1) * BATCH + j) * TPB;
                x4[cur ^ 1][j]  = __ldg(&lg[p4]);
                px4[cur ^ 1][j] = __ldg(&px[p4]);
                py4[cur ^ 1][j] = __ldg(&py[p4]);
            }
        }

        // Compute current batch
        #pragma unroll
        for (int j = 0; j < BATCH; ++j) {
            const int p4 = base + (mi * BATCH + j) * TPB;
            const int h  = p4 / W4;
            const int w  = (p4 - h * W4) * 4;

            const float dx   = X - (float)h;
            const float dx2  = dx * dx;
            const float offx = dx * INV_R2;

            const float xs[4]  = {x4[cur][j].x,  x4[cur][j].y,  x4[cur][j].z,  x4[cur][j].w};
            const float pxs[4] = {px4[cur][j].x, px4[cur][j].y, px4[cur][j].z, px4[cur][j].w};
            const float pys[4] = {py4[cur][j].x, py4[cur][j].y, py4[cur][j].z, py4[cur][j].w};

            #pragma unroll
            for (int k = 0; k < 4; ++k) {
                const float dy   = Y - (float)(w + k);
                const float r2   = fmaf(dy, dy, dx2);
                const float heat = (r2 <= R1SQ) ? 1.0f : 0.0f;

                // BCE-with-logits: softplus(x) - x*heat
                const float x  = xs[k];
                const float sp = fmaxf(x, 0.0f) + __logf(1.0f + __expf(-fabsf(x)));
                s_bce += sp - x * heat;

                // Masked L1 for offsets
                const float vx = fabsf(pxs[k] - offx);
                const float vy = fabsf(pys[k] - dy * INV_R2);
                s_x = fmaf(heat, vx, s_x);
                s_y = fmaf(heat, vy, s_y);
                s_m += heat;
            }
        }
    }

    // Block reduction of 4 accumulators (warp shuffle + smem)
    const unsigned FULL = 0xFFFFFFFFu;
    #pragma unroll
    for (int off = 16; off > 0; off >>= 1) {
        s_bce += __shfl_down_sync(FULL, s_bce, off);
        s_x   += __shfl_down_sync(FULL, s_x,   off);
        s_y   += __shfl_down_sync(FULL, s_y,   off);
        s_m   += __shfl_down_sync(FULL, s_m,   off);
    }

    __shared__ float smem[4][TPB / 32];
    const int lane = threadIdx.x & 31;
    const int wid  = threadIdx.x >> 5;
    if (lane == 0) {
        smem[0][wid] = s_bce;
        smem[1][wid] = s_x;
        smem[2][wid] = s_y;
        smem[3][wid] = s_m;
    }
    __syncthreads();

    if (threadIdx.x == 0) {
        float v0 = 0.0f, v1 = 0.0f, v2 = 0.0f, v3 = 0.0f;
        #pragma unroll
        for (int i = 0; i < TPB / 32; ++i) {
            v0 += smem[0][i];
            v1 += smem[1][i];
            v2 += smem[2][i];
            v3 += smem[3][i];
        }
        g_partial[pair * NCHUNK + chunk] = make_float4(v0, v1, v2, v3);
    }
}

// Epilogue (PDL secondary): waits on primary grid completion device-side, so
// its launch latency overlaps the primary's execution.
__global__ __launch_bounds__(1024) void loss_final_kernel(float* __restrict__ out)
{
#if __CUDA_ARCH__ >= 900
    cudaGridDependencySynchronize();
#endif
    const int t    = threadIdx.x;
    const int w    = t >> 5;
    const int lane = t & 31;
    const unsigned FULL = 0xFFFFFFFFu;

    __shared__ float red[64];
    if (t < 64) red[t] = 0.0f;
    __syncthreads();

    #pragma unroll
    for (int rep = 0; rep < 2; ++rep) {
        const int pair = w + rep * 32;
        if (pair < NPAIR) {
            float sb = 0.0f, sx = 0.0f, sy = 0.0f, sm = 0.0f;
            #pragma unroll
            for (int c = lane; c < NCHUNK; c += 32) {
                const float4 v = g_partial[pair * NCHUNK + c];
                sb += v.x; sx += v.y; sy += v.z; sm += v.w;
            }
            #pragma unroll
            for (int off = 16; off > 0; off >>= 1) {
                sb += __shfl_down_sync(FULL, sb, off);
                sx += __shfl_down_sync(FULL, sx, off);
                sy += __shfl_down_sync(FULL, sy, off);
                sm += __shfl_down_sync(FULL, sm, off);
            }
            if (lane == 0)
                red[pair] = 2.0f * sb / (float)HW + sx / sm + sy / sm;
        }
    }
    __syncthreads();

    if (w == 0) {
        float v = red[lane] + red[32 + lane];   // red[38..63] are zero
        #pragma unroll
        for (int off = 16; off > 0; off >>= 1)
            v += __shfl_down_sync(FULL, v, off);
        if (lane == 0) out[0] = v / (float)NPAIR;
    }
}

extern "C" void kernel_launch(void* const* d_in, const int* in_sizes, int n_in,
                              void* d_out, int out_size)
{
    const float* fm  = (const float*)d_in[0];
    const float* lmk = (const float*)d_in[1];
    float* out = (float*)d_out;

    dim3 grid(NCHUNK, NPAIR);
    loss_main_kernel<<<grid, TPB>>>(fm, lmk);

    // Secondary launch with Programmatic Dependent Launch: overlaps the
    // epilogue's launch latency with the primary's tail. Falls back to a
    // plain serialized launch if PDL launch is unavailable.
    cudaLaunchConfig_t cfg = {};
    cfg.gridDim  = dim3(1, 1, 1);
    cfg.blockDim = dim3(1024, 1, 1);
    cfg.dynamicSmemBytes = 0;
    cfg.stream = 0;
    cudaLaunchAttribute attr[1];
    attr[0].id = cudaLaunchAttributeProgrammaticStreamSerialization;
    attr[0].val.programmaticStreamSerializationAllowed = 1;
    cfg.attrs = attr;
    cfg.numAttrs = 1;
    cudaError_t err = cudaLaunchKernelEx(&cfg, loss_final_kernel, out);
    if (err != cudaSuccess) {
        loss_final_kernel<<<1, 1024>>>(out);
    }
}